// round 1
// baseline (speedup 1.0000x reference)
#include <cuda_runtime.h>
#include <cstdint>

// WindowMultiHeadAttention: B=64, NW=64, L=49, E=384, H=12, hd=32
// One CTA per (b, w) window. Fully fused: x -> qkv -> attention -> context -> out.
// Round 0: fp32 FFMA baseline, zero intermediate HBM traffic.

#define BB   64
#define NWW  64
#define LL   49
#define EE   384
#define HH   12
#define HDD  32
#define QKS  36          // padded row stride for q/k tiles (bank-conflict-free LDS.128)

// smem float offsets
#define OFF_X     0          // 49*384 = 18816
#define OFF_CTX   18816      // 49*384 = 18816
#define OFF_Q     37632      // 49*36  = 1764
#define OFF_K     39396      // 49*36  = 1764
#define OFF_V     41160      // 49*32  = 1568
#define OFF_SC    42728      // 49*49  = 2401
#define OFF_MASK  45129      // 2401
#define OFF_BT    47530      // 169*12 = 2028
#define OFF_REL   49558      // 2401 (int)
#define SMEM_FLOATS 51959
#define SMEM_BYTES  (SMEM_FLOATS * 4)   // 207836

extern __shared__ float smem[];

__global__ __launch_bounds__(384, 1)
void wmha_kernel(const float* __restrict__ x,
                 const float* __restrict__ mask,
                 const float* __restrict__ w_qkv,
                 const float* __restrict__ b_qkv,
                 const float* __restrict__ w_out,
                 const float* __restrict__ b_out,
                 const float* __restrict__ bias_table,
                 const int*   __restrict__ rel_index,
                 float*       __restrict__ out)
{
    const int blk = blockIdx.x;          // b * NW + w
    const int w   = blk & (NWW - 1);
    const int tid = threadIdx.x;

    float* sx    = smem + OFF_X;
    float* sctx  = smem + OFF_CTX;
    float* sq    = smem + OFF_Q;
    float* sk    = smem + OFF_K;
    float* sv    = smem + OFF_V;
    float* ssc   = smem + OFF_SC;
    float* smask = smem + OFF_MASK;
    float* sbt   = smem + OFF_BT;
    int*   srel  = (int*)(smem + OFF_REL);

    // ---- cooperative loads ----
    {
        const float4* xg  = (const float4*)(x + (size_t)blk * (LL * EE));
        float4*       sx4 = (float4*)sx;
        #pragma unroll 4
        for (int i = tid; i < (LL * EE) / 4; i += 384) sx4[i] = xg[i];

        const float* mg = mask + (size_t)w * (LL * LL);
        for (int i = tid; i < LL * LL; i += 384) smask[i] = mg[i];
        for (int i = tid; i < 169 * HH; i += 384) sbt[i]  = bias_table[i];
        for (int i = tid; i < LL * LL; i += 384) srel[i]  = rel_index[i];
    }
    __syncthreads();

    // thread mapping for qkv stage: 96 output columns (3*32) x 4 row-subsets
    const int col   = tid % 96;          // which*32 + d
    const int which = col >> 5;          // 0=q, 1=k, 2=v
    const int d     = col & 31;
    const int isub  = tid / 96;          // 0..3 ; rows isub, isub+4, ...
    const float scale = 0.17677669529663687f;   // 1/sqrt(32)

    for (int h = 0; h < HH; ++h) {
        // ================= QKV projection for head h =================
        {
            const int c = which * EE + h * HDD + d;   // column in (384 x 1152)
            float acc[13];
            const float bq = b_qkv[c];
            #pragma unroll
            for (int r = 0; r < 13; ++r) acc[r] = bq;

            const float* wp = w_qkv + c;
            for (int e = 0; e < EE; e += 4) {
                const float w0 = wp[(size_t)(e + 0) * (3 * EE)];
                const float w1 = wp[(size_t)(e + 1) * (3 * EE)];
                const float w2 = wp[(size_t)(e + 2) * (3 * EE)];
                const float w3 = wp[(size_t)(e + 3) * (3 * EE)];
                #pragma unroll
                for (int r = 0; r < 13; ++r) {
                    const int i = isub + 4 * r;
                    if (i < LL) {
                        const float4 xv = *(const float4*)(sx + i * EE + e);
                        acc[r] += xv.x * w0 + xv.y * w1 + xv.z * w2 + xv.w * w3;
                    }
                }
            }
            float* dst = (which == 0) ? sq : (which == 1) ? sk : sv;
            const int stride = (which == 2) ? HDD : QKS;
            #pragma unroll
            for (int r = 0; r < 13; ++r) {
                const int i = isub + 4 * r;
                if (i < LL) dst[i * stride + d] = acc[r];
            }
        }
        __syncthreads();

        // ================= score = scale*q@k^T + bias + mask =================
        for (int idx = tid; idx < LL * LL; idx += 384) {
            const int i = idx / LL;
            const int j = idx - i * LL;
            const float4* q4 = (const float4*)(sq + i * QKS);
            const float4* k4 = (const float4*)(sk + j * QKS);
            float s = 0.f;
            #pragma unroll
            for (int t = 0; t < 8; ++t) {
                const float4 a = q4[t];
                const float4 b = k4[t];
                s += a.x * b.x + a.y * b.y + a.z * b.z + a.w * b.w;
            }
            ssc[idx] = s * scale + sbt[srel[idx] * HH + h] + smask[idx];
        }
        __syncthreads();

        // ================= softmax over rows =================
        {
            const int warp = tid >> 5;
            const int lane = tid & 31;
            for (int i = warp; i < LL; i += 12) {
                const float v0 = ssc[i * LL + lane];
                const float v1 = (lane < LL - 32) ? ssc[i * LL + 32 + lane] : -1e30f;
                float m = fmaxf(v0, v1);
                #pragma unroll
                for (int o = 16; o > 0; o >>= 1)
                    m = fmaxf(m, __shfl_xor_sync(0xffffffffu, m, o));
                const float e0 = __expf(v0 - m);
                const float e1 = (lane < LL - 32) ? __expf(v1 - m) : 0.f;
                float s = e0 + e1;
                #pragma unroll
                for (int o = 16; o > 0; o >>= 1)
                    s += __shfl_xor_sync(0xffffffffu, s, o);
                const float inv = 1.f / s;
                ssc[i * LL + lane] = e0 * inv;
                if (lane < LL - 32) ssc[i * LL + 32 + lane] = e1 * inv;
            }
        }
        __syncthreads();

        // ================= context_h = alpha @ v =================
        {
            const int dd = tid & 31;
            const int ig = tid >> 5;
            for (int i = ig; i < LL; i += 12) {
                float acc = 0.f;
                const float* arow = ssc + i * LL;
                #pragma unroll 7
                for (int j = 0; j < LL; ++j)
                    acc += arow[j] * sv[j * HDD + dd];
                sctx[i * EE + h * HDD + dd] = acc;
            }
        }
        __syncthreads();   // protect sq/sk/sv/ssc before next head
    }

    // ================= output projection: out = ctx @ w_out + b_out =================
    {
        const int o = tid;   // 0..383, one column per thread
        float acc[LL];
        #pragma unroll
        for (int i = 0; i < LL; ++i) acc[i] = 0.f;

        const float* wp = w_out + o;
        for (int e = 0; e < EE; e += 4) {
            const float w0 = wp[(size_t)(e + 0) * EE];
            const float w1 = wp[(size_t)(e + 1) * EE];
            const float w2 = wp[(size_t)(e + 2) * EE];
            const float w3 = wp[(size_t)(e + 3) * EE];
            #pragma unroll
            for (int i = 0; i < LL; ++i) {
                const float4 c4 = *(const float4*)(sctx + i * EE + e);
                acc[i] += c4.x * w0 + c4.y * w1 + c4.z * w2 + c4.w * w3;
            }
        }
        const float bo = b_out[o];
        float* og = out + (size_t)blk * (LL * EE) + o;
        #pragma unroll
        for (int i = 0; i < LL; ++i) og[i * EE] = acc[i] + bo;
    }
}

extern "C" void kernel_launch(void* const* d_in, const int* in_sizes, int n_in,
                              void* d_out, int out_size)
{
    const float* x    = (const float*)d_in[0];
    const float* mask = (const float*)d_in[1];
    const float* wqkv = (const float*)d_in[2];
    const float* bqkv = (const float*)d_in[3];
    const float* wout = (const float*)d_in[4];
    const float* bout = (const float*)d_in[5];
    const float* bt   = (const float*)d_in[6];
    const int*   rel  = (const int*)d_in[7];
    float* out = (float*)d_out;

    cudaFuncSetAttribute(wmha_kernel,
                         cudaFuncAttributeMaxDynamicSharedMemorySize, SMEM_BYTES);

    wmha_kernel<<<BB * NWW, 384, SMEM_BYTES>>>(
        x, mask, wqkv, bqkv, wout, bout, bt, rel, out);
}

// round 7
// speedup vs baseline: 4.6142x; 4.6142x over previous
#include <cuda_runtime.h>
#include <cstdint>

// WindowMultiHeadAttention  B=64 NW=64 L=49 E=384 H=12 hd=32
// Fully fused per-window kernel: x -> QKV (mma.sync tf32) -> attention (FFMA)
// -> out-proj (mma.sync tf32). Only ~9MB of small __device__ statics.
// R6 fix: A-operand fragment loads now include the K-chunk offset.

#define LL   49
#define EE   384
#define HH   12
#define SCALE 0.17677669529663687f

// smem layout (float offsets)
#define OFF_CTX  0           // 49 x 388
#define OFF_X    19012       // 49 x 388
#define OFF_Q    38024       // 2 x 49 x 36
#define OFF_K    41552       // 2 x 49 x 36
#define OFF_V    45080       // 2 x 52 x 32
#define OFF_BSA  48408       // max(2 x 16 x 200 qkv-B, 2 x 49 x 52 scores)
#define SMEM_FL  54808
#define SMEM_B   (SMEM_FL * 4)       // 219232
#define OFF_BOUT 19012       // out-proj B staging: 2 x 32 x 392 = 25088 fl

// small statics
__device__ float g_wqkv_r[6 * 384 * 192];   // [grp][k][col] pre-scaled
__device__ float g_bqkv_r[6 * 192];
__device__ float g_bm[64 * HH * LL * LL];   // bias + mask fused

__device__ __forceinline__ uint32_t smem_u32(const void* p) {
    uint32_t a;
    asm("{ .reg .u64 t; cvta.to.shared.u64 t, %1; cvt.u32.u64 %0, t; }" : "=r"(a) : "l"(p));
    return a;
}
__device__ __forceinline__ uint32_t lds_tf32(uint32_t addr) {
    uint32_t v;
    asm volatile("ld.shared.b32 %0, [%1];" : "=r"(v) : "r"(addr));
    uint32_t r;
    asm("cvt.rna.tf32.f32 %0, %1;" : "=r"(r) : "f"(__uint_as_float(v)));
    return r;
}
#define CP_ASYNC16(dst, src) \
    asm volatile("cp.async.ca.shared.global [%0], [%1], 16;" :: "r"(dst), "l"(src))
#define CP_COMMIT()  asm volatile("cp.async.commit_group;" ::: "memory")
#define CP_WAIT(n)   asm volatile("cp.async.wait_group %0;" :: "n"(n) : "memory")

__device__ __forceinline__ void mma_tf32(float& c0, float& c1, float& c2, float& c3,
                                         uint32_t a0, uint32_t a1, uint32_t a2, uint32_t a3,
                                         uint32_t b0, uint32_t b1) {
    asm volatile("mma.sync.aligned.m16n8k8.row.col.f32.tf32.tf32.f32 "
        "{%0,%1,%2,%3}, {%4,%5,%6,%7}, {%8,%9}, {%0,%1,%2,%3};"
        : "+f"(c0), "+f"(c1), "+f"(c2), "+f"(c3)
        : "r"(a0), "r"(a1), "r"(a2), "r"(a3), "r"(b0), "r"(b1));
}

// ---------- prep kernels ----------
__global__ void k_reorder(const float* __restrict__ wqkv, const float* __restrict__ bqkv) {
    int idx = blockIdx.x * 256 + threadIdx.x;
    if (idx < 6 * 384 * 192) {
        int grp = idx / (384 * 192);
        int r   = idx - grp * (384 * 192);
        int k   = r / 192;
        int c   = r - k * 192;
        int e = c / 96, rr = c - e * 96, part = rr >> 5, d = rr & 31;
        int h = grp * 2 + e;
        float s = (part == 0) ? SCALE : 1.0f;
        g_wqkv_r[idx] = wqkv[(size_t)k * 1152 + part * 384 + h * 32 + d] * s;
    }
    if (idx < 6 * 192) {
        int grp = idx / 192, c = idx - grp * 192;
        int e = c / 96, rr = c - e * 96, part = rr >> 5, d = rr & 31;
        int h = grp * 2 + e;
        float s = (part == 0) ? SCALE : 1.0f;
        g_bqkv_r[idx] = bqkv[part * 384 + h * 32 + d] * s;
    }
}
__global__ void k_biasmask(const float* __restrict__ table, const int* __restrict__ rel,
                           const float* __restrict__ mask) {
    int idx = blockIdx.x * 256 + threadIdx.x;
    if (idx < 64 * HH * LL * LL) {
        int w  = idx / (HH * LL * LL);
        int r2 = idx - w * (HH * LL * LL);
        int h  = r2 / (LL * LL);
        int ij = r2 - h * (LL * LL);
        g_bm[idx] = table[rel[ij] * HH + h] + mask[(size_t)w * (LL * LL) + ij];
    }
}

// ---------- fused kernel ----------
extern __shared__ float smem[];

__global__ __launch_bounds__(256, 1)
void k_fused(const float* __restrict__ x, const float* __restrict__ w_out,
             const float* __restrict__ b_out, float* __restrict__ out)
{
    const int blk  = blockIdx.x;
    const int tid  = threadIdx.x;
    const int wid  = tid >> 5;
    const int lane = tid & 31;
    const int g    = lane >> 2;       // 0..7
    const int t    = lane & 3;        // 0..3

    const uint32_t sbase = smem_u32(smem);
    float* sctx = smem + OFF_CTX;
    float* sq   = smem + OFF_Q;
    float* sk   = smem + OFF_K;
    float* sv   = smem + OFF_V;
    float* sa   = smem + OFF_BSA;     // aliases qkv B-staging

    const uint32_t sxb   = sbase + OFF_X * 4;
    const uint32_t sctxb = sbase + OFF_CTX * 4;
    const uint32_t sbsab = sbase + OFF_BSA * 4;
    const uint32_t sboutb = sbase + OFF_BOUT * 4;

    // ---- load x tile (49x384) into sx (stride 388) ----
    {
        const float* xg = x + (size_t)blk * (LL * EE);
        for (int u = tid; u < 49 * 96; u += 256) {
            const int row = u / 96, j4 = u - row * 96;
            const float4 v = *(const float4*)(xg + row * EE + j4 * 4);
            *(float4*)(smem + OFF_X + row * 388 + j4 * 4) = v;
        }
    }
    __syncthreads();

    // ================= phase 1: 6 groups of 2 heads =================
    for (int grp = 0; grp < 6; ++grp) {
        const float* Bsrc = g_wqkv_r + (size_t)grp * (384 * 192);

        // prefetch chunk 0 (16 rows x 192 cols) into buf 0
        #pragma unroll
        for (int it = 0; it < 3; ++it) {
            const int u = tid + it * 256;       // < 768
            const int row = u / 48, j4 = u - row * 48;
            CP_ASYNC16(sbsab + (uint32_t)((row * 200 + j4 * 4) * 4),
                       Bsrc + row * 192 + j4 * 4);
        }
        CP_COMMIT();

        float acc[4][3][4];
        #pragma unroll
        for (int a = 0; a < 4; ++a)
            #pragma unroll
            for (int b = 0; b < 3; ++b)
                #pragma unroll
                for (int q = 0; q < 4; ++q) acc[a][b][q] = 0.f;

        const int nb = wid * 24;

        for (int c = 0; c < 24; ++c) {
            if (c < 23) {
                const float* src = Bsrc + (c + 1) * 16 * 192;
                const uint32_t dstb = sbsab + (uint32_t)(((c + 1) & 1) * 3200 * 4);
                #pragma unroll
                for (int it = 0; it < 3; ++it) {
                    const int u = tid + it * 256;
                    const int row = u / 48, j4 = u - row * 48;
                    CP_ASYNC16(dstb + (uint32_t)((row * 200 + j4 * 4) * 4),
                               src + row * 192 + j4 * 4);
                }
                CP_COMMIT();
                CP_WAIT(1);
            } else {
                CP_WAIT(0);
            }
            __syncthreads();

            const uint32_t sB = sbsab + (uint32_t)((c & 1) * 3200 * 4);
            #pragma unroll
            for (int kt = 0; kt < 2; ++kt) {
                uint32_t af[4][4];
                const int kk = c * 16 + kt * 8 + t;      // R6 FIX: chunk offset
                #pragma unroll
                for (int mt = 0; mt < 4; ++mt) {
                    const int r0 = min(mt * 16 + g, 48);
                    const int r1 = min(mt * 16 + g + 8, 48);
                    af[mt][0] = lds_tf32(sxb + (uint32_t)((r0 * 388 + kk) * 4));
                    af[mt][1] = lds_tf32(sxb + (uint32_t)((r1 * 388 + kk) * 4));
                    af[mt][2] = lds_tf32(sxb + (uint32_t)((r0 * 388 + kk + 4) * 4));
                    af[mt][3] = lds_tf32(sxb + (uint32_t)((r1 * 388 + kk + 4) * 4));
                }
                #pragma unroll
                for (int nt = 0; nt < 3; ++nt) {
                    const int col = nb + nt * 8 + g;
                    const uint32_t b0 = lds_tf32(sB + (uint32_t)(((kt * 8 + t) * 200 + col) * 4));
                    const uint32_t b1 = lds_tf32(sB + (uint32_t)(((kt * 8 + t + 4) * 200 + col) * 4));
                    #pragma unroll
                    for (int mt = 0; mt < 4; ++mt)
                        mma_tf32(acc[mt][nt][0], acc[mt][nt][1], acc[mt][nt][2], acc[mt][nt][3],
                                 af[mt][0], af[mt][1], af[mt][2], af[mt][3], b0, b1);
                }
            }
            __syncthreads();
        }

        // ---- epilogue: write q/k/v to smem ----
        #pragma unroll
        for (int mt = 0; mt < 4; ++mt) {
            const int r0 = mt * 16 + g;
            const int r1 = r0 + 8;
            #pragma unroll
            for (int nt = 0; nt < 3; ++nt) {
                const int col0 = nb + nt * 8 + 2 * t;
                const float bb0 = g_bqkv_r[grp * 192 + col0];
                const float bb1 = g_bqkv_r[grp * 192 + col0 + 1];
                const int e = col0 / 96;
                const int rr = col0 - e * 96;
                const int part = rr >> 5;
                const int d = rr & 31;
                float* dst;
                int stride;
                if (part == 0)      { dst = sq + e * 1764; stride = 36; }
                else if (part == 1) { dst = sk + e * 1764; stride = 36; }
                else                { dst = sv + e * 1664; stride = 32; }
                if (r0 < LL) {
                    dst[r0 * stride + d]     = acc[mt][nt][0] + bb0;
                    dst[r0 * stride + d + 1] = acc[mt][nt][1] + bb1;
                }
                if (r1 < LL) {
                    dst[r1 * stride + d]     = acc[mt][nt][2] + bb0;
                    dst[r1 * stride + d + 1] = acc[mt][nt][3] + bb1;
                }
            }
        }
        if (tid < 192) {   // zero v pad rows 49..51
            const int e = tid / 96, r = tid - e * 96;
            sv[e * 1664 + 49 * 32 + r] = 0.f;
        }
        __syncthreads();

        // ---- scores (+bias+mask) : tasks 2*13*13 = 338 ----
        const int h0 = grp * 2;
        for (int u = tid; u < 338; u += 256) {
            const int e = u / 169, r = u - e * 169, ig = r / 13, jg = r - ig * 13;
            const int i0 = ig * 4, j0 = jg * 4;
            const float* qb = sq + e * 1764;
            const float* kb = sk + e * 1764;
            int iq[4], jq[4];
            #pragma unroll
            for (int tt = 0; tt < 4; ++tt) {
                iq[tt] = min(i0 + tt, 48) * 36;
                jq[tt] = min(j0 + tt, 48) * 36;
            }
            float sacc[4][4];
            #pragma unroll
            for (int a = 0; a < 4; ++a)
                #pragma unroll
                for (int b = 0; b < 4; ++b) sacc[a][b] = 0.f;
            #pragma unroll
            for (int kk = 0; kk < 8; ++kk) {
                float4 qf[4], kf[4];
                #pragma unroll
                for (int tt = 0; tt < 4; ++tt) qf[tt] = *(const float4*)(qb + iq[tt] + kk * 4);
                #pragma unroll
                for (int tt = 0; tt < 4; ++tt) kf[tt] = *(const float4*)(kb + jq[tt] + kk * 4);
                #pragma unroll
                for (int a = 0; a < 4; ++a)
                    #pragma unroll
                    for (int b = 0; b < 4; ++b)
                        sacc[a][b] += qf[a].x * kf[b].x + qf[a].y * kf[b].y
                                    + qf[a].z * kf[b].z + qf[a].w * kf[b].w;
            }
            const float* bmb = g_bm + ((size_t)(blk & 63) * HH + (h0 + e)) * (LL * LL);
            float* sae = sa + e * 2548;
            #pragma unroll
            for (int a = 0; a < 4; ++a) {
                const int i = i0 + a;
                if (i < LL)
                    #pragma unroll
                    for (int b = 0; b < 4; ++b) {
                        const int j = j0 + b;
                        if (j < LL) sae[i * 52 + j] = sacc[a][b] + bmb[i * LL + j];
                    }
            }
        }
        __syncthreads();

        // ---- softmax: 98 rows over 8 warps ----
        for (int rr = wid; rr < 2 * LL; rr += 8) {
            const int e = rr / LL, i = rr - e * LL;
            float* row = sa + e * 2548 + i * 52;
            const float v0 = row[lane];
            const float v1 = (lane < 17) ? row[32 + lane] : -1e30f;
            float m = fmaxf(v0, v1);
            #pragma unroll
            for (int o = 16; o > 0; o >>= 1)
                m = fmaxf(m, __shfl_xor_sync(0xffffffffu, m, o));
            const float e0 = __expf(v0 - m);
            const float e1 = (lane < 17) ? __expf(v1 - m) : 0.f;
            float sm = e0 + e1;
            #pragma unroll
            for (int o = 16; o > 0; o >>= 1)
                sm += __shfl_xor_sync(0xffffffffu, sm, o);
            const float inv = 1.f / sm;
            row[lane] = e0 * inv;
            if (lane < 17) row[32 + lane] = e1 * inv;
            if (lane < 3)  row[49 + lane] = 0.f;
        }
        __syncthreads();

        // ---- AV -> sctx : tasks 2*13*8 = 208 ----
        if (tid < 208) {
            const int e = tid / 104, r = tid - e * 104, ig = r / 8, dg = r - ig * 8;
            const int i0 = ig * 4;
            const float* ab = sa + e * 2548;
            const float* vb = sv + e * 1664;
            int ia[4];
            #pragma unroll
            for (int tt = 0; tt < 4; ++tt) ia[tt] = min(i0 + tt, 48) * 52;
            float vacc[4][4];
            #pragma unroll
            for (int a = 0; a < 4; ++a)
                #pragma unroll
                for (int b = 0; b < 4; ++b) vacc[a][b] = 0.f;
            #pragma unroll 13
            for (int j4 = 0; j4 < 13; ++j4) {
                float4 af[4], vf[4];
                #pragma unroll
                for (int tt = 0; tt < 4; ++tt) af[tt] = *(const float4*)(ab + ia[tt] + j4 * 4);
                #pragma unroll
                for (int tt = 0; tt < 4; ++tt) vf[tt] = *(const float4*)(vb + (j4 * 4 + tt) * 32 + dg * 4);
                #pragma unroll
                for (int a = 0; a < 4; ++a) {
                    vacc[a][0] += af[a].x * vf[0].x + af[a].y * vf[1].x + af[a].z * vf[2].x + af[a].w * vf[3].x;
                    vacc[a][1] += af[a].x * vf[0].y + af[a].y * vf[1].y + af[a].z * vf[2].y + af[a].w * vf[3].y;
                    vacc[a][2] += af[a].x * vf[0].z + af[a].y * vf[1].z + af[a].z * vf[2].z + af[a].w * vf[3].z;
                    vacc[a][3] += af[a].x * vf[0].w + af[a].y * vf[1].w + af[a].z * vf[2].w + af[a].w * vf[3].w;
                }
            }
            #pragma unroll
            for (int a = 0; a < 4; ++a) {
                const int i = i0 + a;
                if (i < LL) {
                    float4 o; o.x = vacc[a][0]; o.y = vacc[a][1]; o.z = vacc[a][2]; o.w = vacc[a][3];
                    *(float4*)(sctx + i * 388 + (h0 + e) * 32 + dg * 4) = o;
                }
            }
        }
        __syncthreads();
    }

    // ================= phase 2: out-proj (49x384 @ 384x384) =================
    {
        // prefetch chunk 0: rows 32 x 384 cols of w_out
        #pragma unroll
        for (int it = 0; it < 12; ++it) {
            const int u = tid + it * 256;      // < 3072
            const int row = u / 96, j4 = u - row * 96;
            CP_ASYNC16(sboutb + (uint32_t)((row * 392 + j4 * 4) * 4),
                       w_out + row * 384 + j4 * 4);
        }
        CP_COMMIT();

        float acc[4][6][4];
        #pragma unroll
        for (int a = 0; a < 4; ++a)
            #pragma unroll
            for (int b = 0; b < 6; ++b)
                #pragma unroll
                for (int q = 0; q < 4; ++q) acc[a][b][q] = 0.f;

        for (int c = 0; c < 12; ++c) {
            if (c < 11) {
                const float* src = w_out + (c + 1) * 32 * 384;
                const uint32_t dstb = sboutb + (uint32_t)(((c + 1) & 1) * 12544 * 4);
                #pragma unroll
                for (int it = 0; it < 12; ++it) {
                    const int u = tid + it * 256;
                    const int row = u / 96, j4 = u - row * 96;
                    CP_ASYNC16(dstb + (uint32_t)((row * 392 + j4 * 4) * 4),
                               src + row * 384 + j4 * 4);
                }
                CP_COMMIT();
                CP_WAIT(1);
            } else {
                CP_WAIT(0);
            }
            __syncthreads();

            const uint32_t sB = sboutb + (uint32_t)((c & 1) * 12544 * 4);
            #pragma unroll
            for (int kt = 0; kt < 4; ++kt) {
                uint32_t af[4][4];
                const int kk = c * 32 + kt * 8 + t;      // R6 FIX: chunk offset
                #pragma unroll
                for (int mt = 0; mt < 4; ++mt) {
                    const int r0 = min(mt * 16 + g, 48);
                    const int r1 = min(mt * 16 + g + 8, 48);
                    af[mt][0] = lds_tf32(sctxb + (uint32_t)((r0 * 388 + kk) * 4));
                    af[mt][1] = lds_tf32(sctxb + (uint32_t)((r1 * 388 + kk) * 4));
                    af[mt][2] = lds_tf32(sctxb + (uint32_t)((r0 * 388 + kk + 4) * 4));
                    af[mt][3] = lds_tf32(sctxb + (uint32_t)((r1 * 388 + kk + 4) * 4));
                }
                #pragma unroll
                for (int nt = 0; nt < 6; ++nt) {
                    const int col = wid * 48 + nt * 8 + g;
                    const uint32_t b0 = lds_tf32(sB + (uint32_t)(((kt * 8 + t) * 392 + col) * 4));
                    const uint32_t b1 = lds_tf32(sB + (uint32_t)(((kt * 8 + t + 4) * 392 + col) * 4));
                    #pragma unroll
                    for (int mt = 0; mt < 4; ++mt)
                        mma_tf32(acc[mt][nt][0], acc[mt][nt][1], acc[mt][nt][2], acc[mt][nt][3],
                                 af[mt][0], af[mt][1], af[mt][2], af[mt][3], b0, b1);
                }
            }
            __syncthreads();
        }

        // epilogue -> global
        float* outp = out + (size_t)blk * (LL * EE);
        #pragma unroll
        for (int mt = 0; mt < 4; ++mt) {
            const int r0 = mt * 16 + g;
            const int r1 = r0 + 8;
            #pragma unroll
            for (int nt = 0; nt < 6; ++nt) {
                const int col = wid * 48 + nt * 8 + 2 * t;
                const float b0 = b_out[col], b1 = b_out[col + 1];
                if (r0 < LL) {
                    float2 o; o.x = acc[mt][nt][0] + b0; o.y = acc[mt][nt][1] + b1;
                    *(float2*)(outp + r0 * EE + col) = o;
                }
                if (r1 < LL) {
                    float2 o; o.x = acc[mt][nt][2] + b0; o.y = acc[mt][nt][3] + b1;
                    *(float2*)(outp + r1 * EE + col) = o;
                }
            }
        }
    }
}

// ---------- launch ----------
extern "C" void kernel_launch(void* const* d_in, const int* in_sizes, int n_in,
                              void* d_out, int out_size)
{
    const float* x    = (const float*)d_in[0];
    const float* mask = (const float*)d_in[1];
    const float* wqkv = (const float*)d_in[2];
    const float* bqkv = (const float*)d_in[3];
    const float* wout = (const float*)d_in[4];
    const float* bout = (const float*)d_in[5];
    const float* bt   = (const float*)d_in[6];
    const int*   rel  = (const int*)d_in[7];
    float* out = (float*)d_out;

    cudaFuncSetAttribute(k_fused, cudaFuncAttributeMaxDynamicSharedMemorySize, SMEM_B);

    k_reorder<<<(6 * 384 * 192 + 255) / 256, 256>>>(wqkv, bqkv);
    k_biasmask<<<(64 * HH * LL * LL + 255) / 256, 256>>>(bt, rel, mask);
    k_fused<<<4096, 256, SMEM_B>>>(x, wout, bout, out);
}

// round 8
// speedup vs baseline: 6.3362x; 1.3732x over previous
#include <cuda_runtime.h>
#include <cuda_fp16.h>
#include <cstdint>

// WindowMultiHeadAttention  B=64 NW=64 L=49 E=384 H=12 hd=32
// Fully fused per-window kernel, fp16 mma (m16n8k16, fp32 accum).
// fp16 mantissa == tf32 mantissa (10 bits) -> same accuracy, 2x tensor rate,
// half the LDS + half the weight L2 traffic. Attention math stays fp32.

#define LL   49
#define EE   384
#define HH   12
#define SCALE 0.17677669529663687f

// ---- smem layout in b32 units ----
#define OFF_X    0        // fp16 x:   49 rows x 196 b32 (stride 196 == 4 mod 32)
#define OFF_CTX  9604     // fp16 ctx: 49 x 196
#define OFF_Q    19208    // fp32: 2 x 49 x 36
#define OFF_K    22736    // fp32: 2 x 49 x 36
#define OFF_V    26264    // fp32: 2 x 52 x 32
#define OFF_S1   29592    // phase1 B staging: 2 bufs x 192 cols x 20 b32
#define OFF_SA   37272    // scores: 2 x 49 x 52 fp32
#define SMEM_U32 42368
#define SMEM_B   (SMEM_U32 * 4)    // 169472
#define OFF_S2   19208    // phase2 B staging: 2 x 384 x 20 = 15360 (aliases Q/K/V/S1)

// ---- small statics ----
__device__ __align__(16) __half g_wqkv_h[6 * 192 * 384];  // [grp][col][k], q-part pre-scaled
__device__ __align__(16) __half g_wout_h[384 * 384];      // [col][k]
__device__ float g_bqkv_r[6 * 192];
__device__ float g_bm[64 * HH * LL * LL];                 // bias + mask fused

__device__ __forceinline__ uint32_t smem_u32(const void* p) {
    uint32_t a;
    asm("{ .reg .u64 t; cvta.to.shared.u64 t, %1; cvt.u32.u64 %0, t; }" : "=r"(a) : "l"(p));
    return a;
}
__device__ __forceinline__ uint32_t lds_u32(uint32_t addr) {
    uint32_t v;
    asm volatile("ld.shared.b32 %0, [%1];" : "=r"(v) : "r"(addr));
    return v;
}
__device__ __forceinline__ uint32_t packh2(float a, float b) {
    __half2 h = __float22half2_rn(make_float2(a, b));
    return *(uint32_t*)&h;
}
#define CP_ASYNC16(dst, src) \
    asm volatile("cp.async.cg.shared.global [%0], [%1], 16;" :: "r"(dst), "l"(src))
#define CP_COMMIT()  asm volatile("cp.async.commit_group;" ::: "memory")
#define CP_WAIT(n)   asm volatile("cp.async.wait_group %0;" :: "n"(n) : "memory")

__device__ __forceinline__ void mma_f16(float& c0, float& c1, float& c2, float& c3,
                                        uint32_t a0, uint32_t a1, uint32_t a2, uint32_t a3,
                                        uint32_t b0, uint32_t b1) {
    asm volatile("mma.sync.aligned.m16n8k16.row.col.f32.f16.f16.f32 "
        "{%0,%1,%2,%3}, {%4,%5,%6,%7}, {%8,%9}, {%0,%1,%2,%3};"
        : "+f"(c0), "+f"(c1), "+f"(c2), "+f"(c3)
        : "r"(a0), "r"(a1), "r"(a2), "r"(a3), "r"(b0), "r"(b1));
}

// ---------- single prep kernel ----------
__global__ void k_prep(const float* __restrict__ wqkv, const float* __restrict__ bqkv,
                       const float* __restrict__ wout,
                       const float* __restrict__ table, const int* __restrict__ rel,
                       const float* __restrict__ mask)
{
    const int idx = blockIdx.x * 256 + threadIdx.x;
    if (idx < 6 * 192 * 384) {
        const int grp = idx / (192 * 384);
        const int r   = idx - grp * (192 * 384);
        const int col = r / 384;
        const int k   = r - col * 384;
        const int e = col / 96, rr = col - e * 96, part = rr >> 5, d = rr & 31;
        const int h = grp * 2 + e;
        const float s = (part == 0) ? SCALE : 1.0f;
        g_wqkv_h[idx] = __float2half_rn(wqkv[(size_t)k * 1152 + part * 384 + h * 32 + d] * s);
    }
    if (idx < 384 * 384) {
        const int col = idx / 384, k = idx - col * 384;
        g_wout_h[idx] = __float2half_rn(wout[(size_t)k * 384 + col]);
    }
    if (idx < 1152) {
        const int grp = idx / 192, c = idx - grp * 192;
        const int e = c / 96, rr = c - e * 96, part = rr >> 5, d = rr & 31;
        const int h = grp * 2 + e;
        const float s = (part == 0) ? SCALE : 1.0f;
        g_bqkv_r[idx] = bqkv[part * 384 + h * 32 + d] * s;
    }
    if (idx < 64 * HH * LL * LL) {
        const int w  = idx / (HH * LL * LL);
        const int r2 = idx - w * (HH * LL * LL);
        const int h  = r2 / (LL * LL);
        const int ij = r2 - h * (LL * LL);
        g_bm[idx] = table[rel[ij] * HH + h] + mask[(size_t)w * (LL * LL) + ij];
    }
}

// ---------- fused kernel ----------
extern __shared__ float smem[];

__global__ __launch_bounds__(256, 1)
void k_fused(const float* __restrict__ x, const float* __restrict__ b_out,
             float* __restrict__ out)
{
    const int blk  = blockIdx.x;
    const int tid  = threadIdx.x;
    const int wid  = tid >> 5;
    const int lane = tid & 31;
    const int g    = lane >> 2;       // 0..7
    const int t    = lane & 3;        // 0..3

    const uint32_t sbase = smem_u32(smem);
    float* sq = smem + OFF_Q;
    float* sk = smem + OFF_K;
    float* sv = smem + OFF_V;
    float* sa = smem + OFF_SA;

    const uint32_t sxb   = sbase + OFF_X * 4;
    const uint32_t sctxb = sbase + OFF_CTX * 4;
    const uint32_t s1b   = sbase + OFF_S1 * 4;
    const uint32_t s2b   = sbase + OFF_S2 * 4;

    // ---- load x tile (49x384 fp32 -> fp16, stride 196 b32) ----
    {
        const float* xg = x + (size_t)blk * (LL * EE);
        for (int u = tid; u < 49 * 48; u += 256) {
            const int row = u / 48, j = u - row * 48;
            const float4 v0 = *(const float4*)(xg + row * EE + j * 8);
            const float4 v1 = *(const float4*)(xg + row * EE + j * 8 + 4);
            const uint32_t p0 = packh2(v0.x, v0.y);
            const uint32_t p1 = packh2(v0.z, v0.w);
            const uint32_t p2 = packh2(v1.x, v1.y);
            const uint32_t p3 = packh2(v1.z, v1.w);
            asm volatile("st.shared.v4.b32 [%0], {%1,%2,%3,%4};" ::
                "r"(sxb + (uint32_t)((row * 196 + j * 4) * 4)),
                "r"(p0), "r"(p1), "r"(p2), "r"(p3) : "memory");
        }
    }
    __syncthreads();

    // ================= phase 1: 6 groups of 2 heads =================
    for (int grp = 0; grp < 6; ++grp) {
        const __half* Bsrc = g_wqkv_h + (size_t)grp * (192 * 384);

        // prefetch chunk 0: 192 cols x 32 k (fp16) -> buf 0, stride 20 b32
        #pragma unroll
        for (int it = 0; it < 3; ++it) {
            const int u = tid + it * 256;       // < 768
            const int col = u >> 2, seg = u & 3;
            CP_ASYNC16(s1b + (uint32_t)((col * 20 + seg * 4) * 4),
                       Bsrc + col * 384 + seg * 8);
        }
        CP_COMMIT();

        float acc[4][3][4];
        #pragma unroll
        for (int a = 0; a < 4; ++a)
            #pragma unroll
            for (int b = 0; b < 3; ++b)
                #pragma unroll
                for (int q = 0; q < 4; ++q) acc[a][b][q] = 0.f;

        const int nb = wid * 24;

        for (int c = 0; c < 12; ++c) {
            if (c < 11) {
                const __half* src = Bsrc + (c + 1) * 32;
                const uint32_t dstb = s1b + (uint32_t)(((c + 1) & 1) * 3840 * 4);
                #pragma unroll
                for (int it = 0; it < 3; ++it) {
                    const int u = tid + it * 256;
                    const int col = u >> 2, seg = u & 3;
                    CP_ASYNC16(dstb + (uint32_t)((col * 20 + seg * 4) * 4),
                               src + col * 384 + seg * 8);
                }
                CP_COMMIT();
                CP_WAIT(1);
            } else {
                CP_WAIT(0);
            }
            __syncthreads();

            const uint32_t sB = s1b + (uint32_t)((c & 1) * 3840 * 4);
            #pragma unroll
            for (int kt = 0; kt < 2; ++kt) {
                uint32_t af[4][4];
                const int kkb = c * 16 + kt * 8 + t;     // b32 index along K
                #pragma unroll
                for (int mt = 0; mt < 4; ++mt) {
                    const int r0 = min(mt * 16 + g, 48);
                    const int r1 = min(mt * 16 + g + 8, 48);
                    af[mt][0] = lds_u32(sxb + (uint32_t)((r0 * 196 + kkb) * 4));
                    af[mt][1] = lds_u32(sxb + (uint32_t)((r1 * 196 + kkb) * 4));
                    af[mt][2] = lds_u32(sxb + (uint32_t)((r0 * 196 + kkb) * 4) + 16);
                    af[mt][3] = lds_u32(sxb + (uint32_t)((r1 * 196 + kkb) * 4) + 16);
                }
                #pragma unroll
                for (int nt = 0; nt < 3; ++nt) {
                    const int col = nb + nt * 8 + g;
                    const uint32_t b0 = lds_u32(sB + (uint32_t)((col * 20 + kt * 8 + t) * 4));
                    const uint32_t b1 = lds_u32(sB + (uint32_t)((col * 20 + kt * 8 + t) * 4) + 16);
                    #pragma unroll
                    for (int mt = 0; mt < 4; ++mt)
                        mma_f16(acc[mt][nt][0], acc[mt][nt][1], acc[mt][nt][2], acc[mt][nt][3],
                                af[mt][0], af[mt][1], af[mt][2], af[mt][3], b0, b1);
                }
            }
            __syncthreads();
        }

        // ---- epilogue: write q/k/v (fp32) to smem ----
        #pragma unroll
        for (int mt = 0; mt < 4; ++mt) {
            const int r0 = mt * 16 + g;
            const int r1 = r0 + 8;
            #pragma unroll
            for (int nt = 0; nt < 3; ++nt) {
                const int col0 = nb + nt * 8 + 2 * t;
                const float bb0 = g_bqkv_r[grp * 192 + col0];
                const float bb1 = g_bqkv_r[grp * 192 + col0 + 1];
                const int e = col0 / 96;
                const int rr = col0 - e * 96;
                const int part = rr >> 5;
                const int d = rr & 31;
                float* dst;
                int stride;
                if (part == 0)      { dst = sq + e * 1764; stride = 36; }
                else if (part == 1) { dst = sk + e * 1764; stride = 36; }
                else                { dst = sv + e * 1664; stride = 32; }
                if (r0 < LL) {
                    dst[r0 * stride + d]     = acc[mt][nt][0] + bb0;
                    dst[r0 * stride + d + 1] = acc[mt][nt][1] + bb1;
                }
                if (r1 < LL) {
                    dst[r1 * stride + d]     = acc[mt][nt][2] + bb0;
                    dst[r1 * stride + d + 1] = acc[mt][nt][3] + bb1;
                }
            }
        }
        if (tid < 192) {   // zero v pad rows 49..51
            const int e = tid / 96, r = tid - e * 96;
            sv[e * 1664 + 49 * 32 + r] = 0.f;
        }
        __syncthreads();

        // ---- scores (+bias+mask): tasks 2*13*13 = 338 ----
        const int h0 = grp * 2;
        for (int u = tid; u < 338; u += 256) {
            const int e = u / 169, r = u - e * 169, ig = r / 13, jg = r - ig * 13;
            const int i0 = ig * 4, j0 = jg * 4;
            const float* qb = sq + e * 1764;
            const float* kb = sk + e * 1764;
            int iq[4], jq[4];
            #pragma unroll
            for (int tt = 0; tt < 4; ++tt) {
                iq[tt] = min(i0 + tt, 48) * 36;
                jq[tt] = min(j0 + tt, 48) * 36;
            }
            float sacc[4][4];
            #pragma unroll
            for (int a = 0; a < 4; ++a)
                #pragma unroll
                for (int b = 0; b < 4; ++b) sacc[a][b] = 0.f;
            #pragma unroll
            for (int kk = 0; kk < 8; ++kk) {
                float4 qf[4], kf[4];
                #pragma unroll
                for (int tt = 0; tt < 4; ++tt) qf[tt] = *(const float4*)(qb + iq[tt] + kk * 4);
                #pragma unroll
                for (int tt = 0; tt < 4; ++tt) kf[tt] = *(const float4*)(kb + jq[tt] + kk * 4);
                #pragma unroll
                for (int a = 0; a < 4; ++a)
                    #pragma unroll
                    for (int b = 0; b < 4; ++b)
                        sacc[a][b] += qf[a].x * kf[b].x + qf[a].y * kf[b].y
                                    + qf[a].z * kf[b].z + qf[a].w * kf[b].w;
            }
            const float* bmb = g_bm + ((size_t)(blk & 63) * HH + (h0 + e)) * (LL * LL);
            float* sae = sa + e * 2548;
            #pragma unroll
            for (int a = 0; a < 4; ++a) {
                const int i = i0 + a;
                if (i < LL)
                    #pragma unroll
                    for (int b = 0; b < 4; ++b) {
                        const int j = j0 + b;
                        if (j < LL) sae[i * 52 + j] = sacc[a][b] + bmb[i * LL + j];
                    }
            }
        }
        __syncthreads();

        // ---- softmax: 98 rows / 8 warps ----
        for (int rr = wid; rr < 2 * LL; rr += 8) {
            const int e = rr / LL, i = rr - e * LL;
            float* row = sa + e * 2548 + i * 52;
            const float v0 = row[lane];
            const float v1 = (lane < 17) ? row[32 + lane] : -1e30f;
            float m = fmaxf(v0, v1);
            #pragma unroll
            for (int o = 16; o > 0; o >>= 1)
                m = fmaxf(m, __shfl_xor_sync(0xffffffffu, m, o));
            const float e0 = __expf(v0 - m);
            const float e1 = (lane < 17) ? __expf(v1 - m) : 0.f;
            float sm = e0 + e1;
            #pragma unroll
            for (int o = 16; o > 0; o >>= 1)
                sm += __shfl_xor_sync(0xffffffffu, sm, o);
            const float inv = 1.f / sm;
            row[lane] = e0 * inv;
            if (lane < 17) row[32 + lane] = e1 * inv;
            if (lane < 3)  row[49 + lane] = 0.f;
        }
        __syncthreads();

        // ---- AV -> sctx (fp16): tasks 2*13*8 = 208 ----
        if (tid < 208) {
            const int e = tid / 104, r = tid - e * 104, ig = r / 8, dg = r - ig * 8;
            const int i0 = ig * 4;
            const float* ab = sa + e * 2548;
            const float* vb = sv + e * 1664;
            int ia[4];
            #pragma unroll
            for (int tt = 0; tt < 4; ++tt) ia[tt] = min(i0 + tt, 48) * 52;
            float vacc[4][4];
            #pragma unroll
            for (int a = 0; a < 4; ++a)
                #pragma unroll
                for (int b = 0; b < 4; ++b) vacc[a][b] = 0.f;
            #pragma unroll 13
            for (int j4 = 0; j4 < 13; ++j4) {
                float4 af[4], vf[4];
                #pragma unroll
                for (int tt = 0; tt < 4; ++tt) af[tt] = *(const float4*)(ab + ia[tt] + j4 * 4);
                #pragma unroll
                for (int tt = 0; tt < 4; ++tt) vf[tt] = *(const float4*)(vb + (j4 * 4 + tt) * 32 + dg * 4);
                #pragma unroll
                for (int a = 0; a < 4; ++a) {
                    vacc[a][0] += af[a].x * vf[0].x + af[a].y * vf[1].x + af[a].z * vf[2].x + af[a].w * vf[3].x;
                    vacc[a][1] += af[a].x * vf[0].y + af[a].y * vf[1].y + af[a].z * vf[2].y + af[a].w * vf[3].y;
                    vacc[a][2] += af[a].x * vf[0].z + af[a].y * vf[1].z + af[a].z * vf[2].z + af[a].w * vf[3].z;
                    vacc[a][3] += af[a].x * vf[0].w + af[a].y * vf[1].w + af[a].z * vf[2].w + af[a].w * vf[3].w;
                }
            }
            #pragma unroll
            for (int a = 0; a < 4; ++a) {
                const int i = i0 + a;
                if (i < LL) {
                    const uint32_t p0 = packh2(vacc[a][0], vacc[a][1]);
                    const uint32_t p1 = packh2(vacc[a][2], vacc[a][3]);
                    asm volatile("st.shared.v2.b32 [%0], {%1,%2};" ::
                        "r"(sctxb + (uint32_t)((i * 196 + (h0 + e) * 16 + dg * 2) * 4)),
                        "r"(p0), "r"(p1) : "memory");
                }
            }
        }
        __syncthreads();
    }

    // ================= phase 2: out-proj (49x384 @ 384x384) =================
    {
        // prefetch chunk 0: 384 cols x 32 k fp16 -> buf 0
        #pragma unroll
        for (int it = 0; it < 6; ++it) {
            const int u = tid + it * 256;      // < 1536
            const int col = u >> 2, seg = u & 3;
            CP_ASYNC16(s2b + (uint32_t)((col * 20 + seg * 4) * 4),
                       g_wout_h + col * 384 + seg * 8);
        }
        CP_COMMIT();

        float acc[4][6][4];
        #pragma unroll
        for (int a = 0; a < 4; ++a)
            #pragma unroll
            for (int b = 0; b < 6; ++b)
                #pragma unroll
                for (int q = 0; q < 4; ++q) acc[a][b][q] = 0.f;

        for (int c = 0; c < 12; ++c) {
            if (c < 11) {
                const __half* src = g_wout_h + (c + 1) * 32;
                const uint32_t dstb = s2b + (uint32_t)(((c + 1) & 1) * 7680 * 4);
                #pragma unroll
                for (int it = 0; it < 6; ++it) {
                    const int u = tid + it * 256;
                    const int col = u >> 2, seg = u & 3;
                    CP_ASYNC16(dstb + (uint32_t)((col * 20 + seg * 4) * 4),
                               src + col * 384 + seg * 8);
                }
                CP_COMMIT();
                CP_WAIT(1);
            } else {
                CP_WAIT(0);
            }
            __syncthreads();

            const uint32_t sB = s2b + (uint32_t)((c & 1) * 7680 * 4);
            #pragma unroll
            for (int kt = 0; kt < 2; ++kt) {
                uint32_t af[4][4];
                const int kkb = c * 16 + kt * 8 + t;
                #pragma unroll
                for (int mt = 0; mt < 4; ++mt) {
                    const int r0 = min(mt * 16 + g, 48);
                    const int r1 = min(mt * 16 + g + 8, 48);
                    af[mt][0] = lds_u32(sctxb + (uint32_t)((r0 * 196 + kkb) * 4));
                    af[mt][1] = lds_u32(sctxb + (uint32_t)((r1 * 196 + kkb) * 4));
                    af[mt][2] = lds_u32(sctxb + (uint32_t)((r0 * 196 + kkb) * 4) + 16);
                    af[mt][3] = lds_u32(sctxb + (uint32_t)((r1 * 196 + kkb) * 4) + 16);
                }
                #pragma unroll
                for (int nt = 0; nt < 6; ++nt) {
                    const int col = wid * 48 + nt * 8 + g;
                    const uint32_t b0 = lds_u32(sB + (uint32_t)((col * 20 + kt * 8 + t) * 4));
                    const uint32_t b1 = lds_u32(sB + (uint32_t)((col * 20 + kt * 8 + t) * 4) + 16);
                    #pragma unroll
                    for (int mt = 0; mt < 4; ++mt)
                        mma_f16(acc[mt][nt][0], acc[mt][nt][1], acc[mt][nt][2], acc[mt][nt][3],
                                af[mt][0], af[mt][1], af[mt][2], af[mt][3], b0, b1);
                }
            }
            __syncthreads();
        }

        // epilogue -> global
        float* outp = out + (size_t)blk * (LL * EE);
        #pragma unroll
        for (int mt = 0; mt < 4; ++mt) {
            const int r0 = mt * 16 + g;
            const int r1 = r0 + 8;
            #pragma unroll
            for (int nt = 0; nt < 6; ++nt) {
                const int col = wid * 48 + nt * 8 + 2 * t;
                const float b0 = b_out[col], b1 = b_out[col + 1];
                if (r0 < LL) {
                    float2 o; o.x = acc[mt][nt][0] + b0; o.y = acc[mt][nt][1] + b1;
                    *(float2*)(outp + r0 * EE + col) = o;
                }
                if (r1 < LL) {
                    float2 o; o.x = acc[mt][nt][2] + b0; o.y = acc[mt][nt][3] + b1;
                    *(float2*)(outp + r1 * EE + col) = o;
                }
            }
        }
    }
}

// ---------- launch ----------
extern "C" void kernel_launch(void* const* d_in, const int* in_sizes, int n_in,
                              void* d_out, int out_size)
{
    const float* x    = (const float*)d_in[0];
    const float* mask = (const float*)d_in[1];
    const float* wqkv = (const float*)d_in[2];
    const float* bqkv = (const float*)d_in[3];
    const float* wout = (const float*)d_in[4];
    const float* bout = (const float*)d_in[5];
    const float* bt   = (const float*)d_in[6];
    const int*   rel  = (const int*)d_in[7];
    float* out = (float*)d_out;

    cudaFuncSetAttribute(k_fused, cudaFuncAttributeMaxDynamicSharedMemorySize, SMEM_B);

    k_prep<<<(64 * HH * LL * LL + 255) / 256, 256>>>(wqkv, bqkv, wout, bt, rel, mask);
    k_fused<<<4096, 256, SMEM_B>>>(x, bout, out);
}

// round 9
// speedup vs baseline: 6.9028x; 1.0894x over previous
#include <cuda_runtime.h>
#include <cuda_fp16.h>
#include <cstdint>

// WindowMultiHeadAttention  B=64 NW=64 L=49 E=384 H=12 hd=32
// Fully fused per-window kernel, fp16 mma (m16n8k16, fp32 accum), 512 threads.
// R9: 256->512 threads per CTA (16 warps, 4/SMSP) to fix occupancy/latency binding.

#define LL   49
#define EE   384
#define HH   12
#define SCALE 0.17677669529663687f
#define NTHR 512

// ---- smem layout in b32 units ----
#define OFF_X    0        // fp16 x:   49 rows x 196 b32
#define OFF_CTX  9604     // fp16 ctx: 49 x 196
#define OFF_Q    19208    // fp32: 2 x 49 x 36
#define OFF_K    22736    // fp32: 2 x 49 x 36
#define OFF_V    26264    // fp32: 2 x 52 x 32
#define OFF_S1   29592    // phase1 B staging: 2 bufs x 192 cols x 20 b32
#define OFF_SA   37272    // scores: 2 x 49 x 52 fp32
#define SMEM_U32 42368
#define SMEM_B   (SMEM_U32 * 4)    // 169472
#define OFF_S2   19208    // phase2 B staging: 2 x 384 x 20 = 15360 (aliases Q/K/V/S1)

// ---- small statics ----
__device__ __align__(16) __half g_wqkv_h[6 * 192 * 384];  // [grp][col][k], q-part pre-scaled
__device__ __align__(16) __half g_wout_h[384 * 384];      // [col][k]
__device__ float g_bqkv_r[6 * 192];
__device__ float g_bm[64 * HH * LL * LL];                 // bias + mask fused

__device__ __forceinline__ uint32_t smem_u32(const void* p) {
    uint32_t a;
    asm("{ .reg .u64 t; cvta.to.shared.u64 t, %1; cvt.u32.u64 %0, t; }" : "=r"(a) : "l"(p));
    return a;
}
__device__ __forceinline__ uint32_t lds_u32(uint32_t addr) {
    uint32_t v;
    asm volatile("ld.shared.b32 %0, [%1];" : "=r"(v) : "r"(addr));
    return v;
}
__device__ __forceinline__ uint32_t packh2(float a, float b) {
    __half2 h = __float22half2_rn(make_float2(a, b));
    return *(uint32_t*)&h;
}
#define CP_ASYNC16(dst, src) \
    asm volatile("cp.async.cg.shared.global [%0], [%1], 16;" :: "r"(dst), "l"(src))
#define CP_COMMIT()  asm volatile("cp.async.commit_group;" ::: "memory")
#define CP_WAIT(n)   asm volatile("cp.async.wait_group %0;" :: "n"(n) : "memory")

__device__ __forceinline__ void mma_f16(float& c0, float& c1, float& c2, float& c3,
                                        uint32_t a0, uint32_t a1, uint32_t a2, uint32_t a3,
                                        uint32_t b0, uint32_t b1) {
    asm volatile("mma.sync.aligned.m16n8k16.row.col.f32.f16.f16.f32 "
        "{%0,%1,%2,%3}, {%4,%5,%6,%7}, {%8,%9}, {%0,%1,%2,%3};"
        : "+f"(c0), "+f"(c1), "+f"(c2), "+f"(c3)
        : "r"(a0), "r"(a1), "r"(a2), "r"(a3), "r"(b0), "r"(b1));
}

// ---------- single prep kernel ----------
__global__ void k_prep(const float* __restrict__ wqkv, const float* __restrict__ bqkv,
                       const float* __restrict__ wout,
                       const float* __restrict__ table, const int* __restrict__ rel,
                       const float* __restrict__ mask)
{
    const int idx = blockIdx.x * 256 + threadIdx.x;
    if (idx < 6 * 192 * 384) {
        const int grp = idx / (192 * 384);
        const int r   = idx - grp * (192 * 384);
        const int col = r / 384;
        const int k   = r - col * 384;
        const int e = col / 96, rr = col - e * 96, part = rr >> 5, d = rr & 31;
        const int h = grp * 2 + e;
        const float s = (part == 0) ? SCALE : 1.0f;
        g_wqkv_h[idx] = __float2half_rn(wqkv[(size_t)k * 1152 + part * 384 + h * 32 + d] * s);
    }
    if (idx < 384 * 384) {
        const int col = idx / 384, k = idx - col * 384;
        g_wout_h[idx] = __float2half_rn(wout[(size_t)k * 384 + col]);
    }
    if (idx < 1152) {
        const int grp = idx / 192, c = idx - grp * 192;
        const int e = c / 96, rr = c - e * 96, part = rr >> 5, d = rr & 31;
        const int h = grp * 2 + e;
        const float s = (part == 0) ? SCALE : 1.0f;
        g_bqkv_r[idx] = bqkv[part * 384 + h * 32 + d] * s;
    }
    if (idx < 64 * HH * LL * LL) {
        const int w  = idx / (HH * LL * LL);
        const int r2 = idx - w * (HH * LL * LL);
        const int h  = r2 / (LL * LL);
        const int ij = r2 - h * (LL * LL);
        g_bm[idx] = table[rel[ij] * HH + h] + mask[(size_t)w * (LL * LL) + ij];
    }
}

// ---------- fused kernel ----------
extern __shared__ float smem[];

__global__ __launch_bounds__(NTHR, 1)
void k_fused(const float* __restrict__ x, const float* __restrict__ b_out,
             float* __restrict__ out)
{
    const int blk  = blockIdx.x;
    const int tid  = threadIdx.x;
    const int wid  = tid >> 5;        // 0..15
    const int lane = tid & 31;
    const int g    = lane >> 2;       // 0..7
    const int t    = lane & 3;        // 0..3
    const int wm   = wid >> 3;        // 0..1  (M half)
    const int wn   = wid & 7;         // 0..7  (N slice)

    const uint32_t sbase = smem_u32(smem);
    float* sq = smem + OFF_Q;
    float* sk = smem + OFF_K;
    float* sv = smem + OFF_V;
    float* sa = smem + OFF_SA;

    const uint32_t sxb   = sbase + OFF_X * 4;
    const uint32_t sctxb = sbase + OFF_CTX * 4;
    const uint32_t s1b   = sbase + OFF_S1 * 4;
    const uint32_t s2b   = sbase + OFF_S2 * 4;

    // ---- load x tile (49x384 fp32 -> fp16, stride 196 b32) ----
    {
        const float* xg = x + (size_t)blk * (LL * EE);
        for (int u = tid; u < 49 * 48; u += NTHR) {
            const int row = u / 48, j = u - row * 48;
            const float4 v0 = *(const float4*)(xg + row * EE + j * 8);
            const float4 v1 = *(const float4*)(xg + row * EE + j * 8 + 4);
            const uint32_t p0 = packh2(v0.x, v0.y);
            const uint32_t p1 = packh2(v0.z, v0.w);
            const uint32_t p2 = packh2(v1.x, v1.y);
            const uint32_t p3 = packh2(v1.z, v1.w);
            asm volatile("st.shared.v4.b32 [%0], {%1,%2,%3,%4};" ::
                "r"(sxb + (uint32_t)((row * 196 + j * 4) * 4)),
                "r"(p0), "r"(p1), "r"(p2), "r"(p3) : "memory");
        }
    }
    __syncthreads();

    // ================= phase 1: 6 groups of 2 heads =================
    for (int grp = 0; grp < 6; ++grp) {
        const __half* Bsrc = g_wqkv_h + (size_t)grp * (192 * 384);

        // prefetch chunk 0: 192 cols x 32 k (fp16) -> buf 0, stride 20 b32
        #pragma unroll
        for (int it = 0; it < 2; ++it) {
            const int u = tid + it * NTHR;
            if (u < 768) {
                const int col = u >> 2, seg = u & 3;
                CP_ASYNC16(s1b + (uint32_t)((col * 20 + seg * 4) * 4),
                           Bsrc + col * 384 + seg * 8);
            }
        }
        CP_COMMIT();

        float acc[2][3][4];
        #pragma unroll
        for (int a = 0; a < 2; ++a)
            #pragma unroll
            for (int b = 0; b < 3; ++b)
                #pragma unroll
                for (int q = 0; q < 4; ++q) acc[a][b][q] = 0.f;

        const int nb = wn * 24;

        for (int c = 0; c < 12; ++c) {
            if (c < 11) {
                const __half* src = Bsrc + (c + 1) * 32;
                const uint32_t dstb = s1b + (uint32_t)(((c + 1) & 1) * 3840 * 4);
                #pragma unroll
                for (int it = 0; it < 2; ++it) {
                    const int u = tid + it * NTHR;
                    if (u < 768) {
                        const int col = u >> 2, seg = u & 3;
                        CP_ASYNC16(dstb + (uint32_t)((col * 20 + seg * 4) * 4),
                                   src + col * 384 + seg * 8);
                    }
                }
                CP_COMMIT();
                CP_WAIT(1);
            } else {
                CP_WAIT(0);
            }
            __syncthreads();

            const uint32_t sB = s1b + (uint32_t)((c & 1) * 3840 * 4);
            #pragma unroll
            for (int kt = 0; kt < 2; ++kt) {
                uint32_t af[2][4];
                const int kkb = c * 16 + kt * 8 + t;     // b32 index along K
                #pragma unroll
                for (int mt = 0; mt < 2; ++mt) {
                    const int r0 = min(wm * 32 + mt * 16 + g, 48);
                    const int r1 = min(wm * 32 + mt * 16 + g + 8, 48);
                    af[mt][0] = lds_u32(sxb + (uint32_t)((r0 * 196 + kkb) * 4));
                    af[mt][1] = lds_u32(sxb + (uint32_t)((r1 * 196 + kkb) * 4));
                    af[mt][2] = lds_u32(sxb + (uint32_t)((r0 * 196 + kkb) * 4) + 16);
                    af[mt][3] = lds_u32(sxb + (uint32_t)((r1 * 196 + kkb) * 4) + 16);
                }
                #pragma unroll
                for (int nt = 0; nt < 3; ++nt) {
                    const int col = nb + nt * 8 + g;
                    const uint32_t b0 = lds_u32(sB + (uint32_t)((col * 20 + kt * 8 + t) * 4));
                    const uint32_t b1 = lds_u32(sB + (uint32_t)((col * 20 + kt * 8 + t) * 4) + 16);
                    #pragma unroll
                    for (int mt = 0; mt < 2; ++mt)
                        mma_f16(acc[mt][nt][0], acc[mt][nt][1], acc[mt][nt][2], acc[mt][nt][3],
                                af[mt][0], af[mt][1], af[mt][2], af[mt][3], b0, b1);
                }
            }
            __syncthreads();
        }

        // ---- epilogue: write q/k/v (fp32) to smem ----
        #pragma unroll
        for (int mt = 0; mt < 2; ++mt) {
            const int r0 = wm * 32 + mt * 16 + g;
            const int r1 = r0 + 8;
            #pragma unroll
            for (int nt = 0; nt < 3; ++nt) {
                const int col0 = nb + nt * 8 + 2 * t;
                const float bb0 = g_bqkv_r[grp * 192 + col0];
                const float bb1 = g_bqkv_r[grp * 192 + col0 + 1];
                const int e = col0 / 96;
                const int rr = col0 - e * 96;
                const int part = rr >> 5;
                const int d = rr & 31;
                float* dst;
                int stride;
                if (part == 0)      { dst = sq + e * 1764; stride = 36; }
                else if (part == 1) { dst = sk + e * 1764; stride = 36; }
                else                { dst = sv + e * 1664; stride = 32; }
                if (r0 < LL) {
                    dst[r0 * stride + d]     = acc[mt][nt][0] + bb0;
                    dst[r0 * stride + d + 1] = acc[mt][nt][1] + bb1;
                }
                if (r1 < LL) {
                    dst[r1 * stride + d]     = acc[mt][nt][2] + bb0;
                    dst[r1 * stride + d + 1] = acc[mt][nt][3] + bb1;
                }
            }
        }
        if (tid < 192) {   // zero v pad rows 49..51
            const int e = tid / 96, r = tid - e * 96;
            sv[e * 1664 + 49 * 32 + r] = 0.f;
        }
        __syncthreads();

        // ---- scores (+bias+mask): tasks 2*13*13 = 338 ----
        const int h0 = grp * 2;
        if (tid < 338) {
            const int u = tid;
            const int e = u / 169, r = u - e * 169, ig = r / 13, jg = r - ig * 13;
            const int i0 = ig * 4, j0 = jg * 4;
            const float* qb = sq + e * 1764;
            const float* kb = sk + e * 1764;
            int iq[4], jq[4];
            #pragma unroll
            for (int tt = 0; tt < 4; ++tt) {
                iq[tt] = min(i0 + tt, 48) * 36;
                jq[tt] = min(j0 + tt, 48) * 36;
            }
            float sacc[4][4];
            #pragma unroll
            for (int a = 0; a < 4; ++a)
                #pragma unroll
                for (int b = 0; b < 4; ++b) sacc[a][b] = 0.f;
            #pragma unroll
            for (int kk = 0; kk < 8; ++kk) {
                float4 qf[4], kf[4];
                #pragma unroll
                for (int tt = 0; tt < 4; ++tt) qf[tt] = *(const float4*)(qb + iq[tt] + kk * 4);
                #pragma unroll
                for (int tt = 0; tt < 4; ++tt) kf[tt] = *(const float4*)(kb + jq[tt] + kk * 4);
                #pragma unroll
                for (int a = 0; a < 4; ++a)
                    #pragma unroll
                    for (int b = 0; b < 4; ++b)
                        sacc[a][b] += qf[a].x * kf[b].x + qf[a].y * kf[b].y
                                    + qf[a].z * kf[b].z + qf[a].w * kf[b].w;
            }
            const float* bmb = g_bm + ((size_t)(blk & 63) * HH + (h0 + e)) * (LL * LL);
            float* sae = sa + e * 2548;
            #pragma unroll
            for (int a = 0; a < 4; ++a) {
                const int i = i0 + a;
                if (i < LL)
                    #pragma unroll
                    for (int b = 0; b < 4; ++b) {
                        const int j = j0 + b;
                        if (j < LL) sae[i * 52 + j] = sacc[a][b] + bmb[i * LL + j];
                    }
            }
        }
        __syncthreads();

        // ---- softmax: 98 rows / 16 warps ----
        for (int rr = wid; rr < 2 * LL; rr += 16) {
            const int e = rr / LL, i = rr - e * LL;
            float* row = sa + e * 2548 + i * 52;
            const float v0 = row[lane];
            const float v1 = (lane < 17) ? row[32 + lane] : -1e30f;
            float m = fmaxf(v0, v1);
            #pragma unroll
            for (int o = 16; o > 0; o >>= 1)
                m = fmaxf(m, __shfl_xor_sync(0xffffffffu, m, o));
            const float e0 = __expf(v0 - m);
            const float e1 = (lane < 17) ? __expf(v1 - m) : 0.f;
            float sm = e0 + e1;
            #pragma unroll
            for (int o = 16; o > 0; o >>= 1)
                sm += __shfl_xor_sync(0xffffffffu, sm, o);
            const float inv = 1.f / sm;
            row[lane] = e0 * inv;
            if (lane < 17) row[32 + lane] = e1 * inv;
            if (lane < 3)  row[49 + lane] = 0.f;
        }
        __syncthreads();

        // ---- AV -> sctx (fp16): tasks 2*13*8 = 208 ----
        if (tid < 208) {
            const int e = tid / 104, r = tid - e * 104, ig = r / 8, dg = r - ig * 8;
            const int i0 = ig * 4;
            const float* ab = sa + e * 2548;
            const float* vb = sv + e * 1664;
            int ia[4];
            #pragma unroll
            for (int tt = 0; tt < 4; ++tt) ia[tt] = min(i0 + tt, 48) * 52;
            float vacc[4][4];
            #pragma unroll
            for (int a = 0; a < 4; ++a)
                #pragma unroll
                for (int b = 0; b < 4; ++b) vacc[a][b] = 0.f;
            #pragma unroll 13
            for (int j4 = 0; j4 < 13; ++j4) {
                float4 af[4], vf[4];
                #pragma unroll
                for (int tt = 0; tt < 4; ++tt) af[tt] = *(const float4*)(ab + ia[tt] + j4 * 4);
                #pragma unroll
                for (int tt = 0; tt < 4; ++tt) vf[tt] = *(const float4*)(vb + (j4 * 4 + tt) * 32 + dg * 4);
                #pragma unroll
                for (int a = 0; a < 4; ++a) {
                    vacc[a][0] += af[a].x * vf[0].x + af[a].y * vf[1].x + af[a].z * vf[2].x + af[a].w * vf[3].x;
                    vacc[a][1] += af[a].x * vf[0].y + af[a].y * vf[1].y + af[a].z * vf[2].y + af[a].w * vf[3].y;
                    vacc[a][2] += af[a].x * vf[0].z + af[a].y * vf[1].z + af[a].z * vf[2].z + af[a].w * vf[3].z;
                    vacc[a][3] += af[a].x * vf[0].w + af[a].y * vf[1].w + af[a].z * vf[2].w + af[a].w * vf[3].w;
                }
            }
            #pragma unroll
            for (int a = 0; a < 4; ++a) {
                const int i = i0 + a;
                if (i < LL) {
                    const uint32_t p0 = packh2(vacc[a][0], vacc[a][1]);
                    const uint32_t p1 = packh2(vacc[a][2], vacc[a][3]);
                    asm volatile("st.shared.v2.b32 [%0], {%1,%2};" ::
                        "r"(sctxb + (uint32_t)((i * 196 + (h0 + e) * 16 + dg * 2) * 4)),
                        "r"(p0), "r"(p1) : "memory");
                }
            }
        }
        __syncthreads();
    }

    // ================= phase 2: out-proj (49x384 @ 384x384) =================
    {
        // prefetch chunk 0: 384 cols x 32 k fp16 -> buf 0
        #pragma unroll
        for (int it = 0; it < 3; ++it) {
            const int u = tid + it * NTHR;
            if (u < 1536) {
                const int col = u >> 2, seg = u & 3;
                CP_ASYNC16(s2b + (uint32_t)((col * 20 + seg * 4) * 4),
                           g_wout_h + col * 384 + seg * 8);
            }
        }
        CP_COMMIT();

        float acc[2][6][4];
        #pragma unroll
        for (int a = 0; a < 2; ++a)
            #pragma unroll
            for (int b = 0; b < 6; ++b)
                #pragma unroll
                for (int q = 0; q < 4; ++q) acc[a][b][q] = 0.f;

        for (int c = 0; c < 12; ++c) {
            if (c < 11) {
                const __half* src = g_wout_h + (c + 1) * 32;
                const uint32_t dstb = s2b + (uint32_t)(((c + 1) & 1) * 7680 * 4);
                #pragma unroll
                for (int it = 0; it < 3; ++it) {
                    const int u = tid + it * NTHR;
                    if (u < 1536) {
                        const int col = u >> 2, seg = u & 3;
                        CP_ASYNC16(dstb + (uint32_t)((col * 20 + seg * 4) * 4),
                                   src + col * 384 + seg * 8);
                    }
                }
                CP_COMMIT();
                CP_WAIT(1);
            } else {
                CP_WAIT(0);
            }
            __syncthreads();

            const uint32_t sB = s2b + (uint32_t)((c & 1) * 7680 * 4);
            #pragma unroll
            for (int kt = 0; kt < 2; ++kt) {
                uint32_t af[2][4];
                const int kkb = c * 16 + kt * 8 + t;
                #pragma unroll
                for (int mt = 0; mt < 2; ++mt) {
                    const int r0 = min(wm * 32 + mt * 16 + g, 48);
                    const int r1 = min(wm * 32 + mt * 16 + g + 8, 48);
                    af[mt][0] = lds_u32(sctxb + (uint32_t)((r0 * 196 + kkb) * 4));
                    af[mt][1] = lds_u32(sctxb + (uint32_t)((r1 * 196 + kkb) * 4));
                    af[mt][2] = lds_u32(sctxb + (uint32_t)((r0 * 196 + kkb) * 4) + 16);
                    af[mt][3] = lds_u32(sctxb + (uint32_t)((r1 * 196 + kkb) * 4) + 16);
                }
                #pragma unroll
                for (int nt = 0; nt < 6; ++nt) {
                    const int col = wn * 48 + nt * 8 + g;
                    const uint32_t b0 = lds_u32(sB + (uint32_t)((col * 20 + kt * 8 + t) * 4));
                    const uint32_t b1 = lds_u32(sB + (uint32_t)((col * 20 + kt * 8 + t) * 4) + 16);
                    #pragma unroll
                    for (int mt = 0; mt < 2; ++mt)
                        mma_f16(acc[mt][nt][0], acc[mt][nt][1], acc[mt][nt][2], acc[mt][nt][3],
                                af[mt][0], af[mt][1], af[mt][2], af[mt][3], b0, b1);
                }
            }
            __syncthreads();
        }

        // epilogue -> global
        float* outp = out + (size_t)blk * (LL * EE);
        #pragma unroll
        for (int mt = 0; mt < 2; ++mt) {
            const int r0 = wm * 32 + mt * 16 + g;
            const int r1 = r0 + 8;
            #pragma unroll
            for (int nt = 0; nt < 6; ++nt) {
                const int col = wn * 48 + nt * 8 + 2 * t;
                const float b0 = b_out[col], b1 = b_out[col + 1];
                if (r0 < LL) {
                    float2 o; o.x = acc[mt][nt][0] + b0; o.y = acc[mt][nt][1] + b1;
                    *(float2*)(outp + r0 * EE + col) = o;
                }
                if (r1 < LL) {
                    float2 o; o.x = acc[mt][nt][2] + b0; o.y = acc[mt][nt][3] + b1;
                    *(float2*)(outp + r1 * EE + col) = o;
                }
            }
        }
    }
}

// ---------- launch ----------
extern "C" void kernel_launch(void* const* d_in, const int* in_sizes, int n_in,
                              void* d_out, int out_size)
{
    const float* x    = (const float*)d_in[0];
    const float* mask = (const float*)d_in[1];
    const float* wqkv = (const float*)d_in[2];
    const float* bqkv = (const float*)d_in[3];
    const float* wout = (const float*)d_in[4];
    const float* bout = (const float*)d_in[5];
    const float* bt   = (const float*)d_in[6];
    const int*   rel  = (const int*)d_in[7];
    float* out = (float*)d_out;

    cudaFuncSetAttribute(k_fused, cudaFuncAttributeMaxDynamicSharedMemorySize, SMEM_B);

    k_prep<<<(64 * HH * LL * LL + 255) / 256, 256>>>(wqkv, bqkv, wout, bt, rel, mask);
    k_fused<<<4096, NTHR, SMEM_B>>>(x, bout, out);
}

// round 10
// speedup vs baseline: 9.8519x; 1.4272x over previous
#include <cuda_runtime.h>
#include <cuda_fp16.h>
#include <cstdint>

// WindowMultiHeadAttention  B=64 NW=64 L=49 E=384 H=12 hd=32
// Fully fused per-window kernel. ALL GEMMs (QKV, scores, AV, out-proj) on
// fp16 mma.sync (fp32 accum). R10: tensor-core attention + fewer barriers.

#define LL   49
#define EE   384
#define HH   12
#define SCALE 0.17677669529663687f
#define NTHR 512

// ---- smem layout (b32 units) ----
#define OFF_X    0            // fp16 x:   49 x 196
#define OFF_CTX  9604         // fp16 ctx: 49 x 196
#define OFF_QH   19208        // fp16 q:   2 x 49 x 20
#define OFF_KH   21168        // fp16 k:   2 x 56 x 20
#define OFF_VT   23408        // fp16 vT:  2 x 32 x 36  (d rows, j cols padded 64)
#define OFF_AL   25712        // fp16 alpha: 2 x 49 x 36 (j padded 64)
#define OFF_SA   29240        // fp32 scores: 2 x 49 x 52
#define OFF_S1   34336        // phase1 B staging: 2 x 192 x 52
#define S1_BUF   9984
#define SMEM_U32 54304
#define SMEM_B   (SMEM_U32 * 4)   // 217216
#define OFF_S2   19208        // phase2 B staging: 2 x 384 x 36 (aliases QH..S1)
#define S2_BUF   13824

__device__ __align__(16) __half g_wqkv_h[6 * 192 * 384];  // [grp][col][k], q pre-scaled
__device__ __align__(16) __half g_wout_h[384 * 384];      // [col][k]
__device__ float g_bqkv_r[6 * 192];
__device__ float g_bm[64 * HH * LL * LL];

__device__ __forceinline__ uint32_t smem_u32(const void* p) {
    uint32_t a;
    asm("{ .reg .u64 t; cvta.to.shared.u64 t, %1; cvt.u32.u64 %0, t; }" : "=r"(a) : "l"(p));
    return a;
}
__device__ __forceinline__ uint32_t lds_u32(uint32_t addr) {
    uint32_t v;
    asm volatile("ld.shared.b32 %0, [%1];" : "=r"(v) : "r"(addr));
    return v;
}
__device__ __forceinline__ void sts_h(uint32_t addr, float f) {
    __half h = __float2half_rn(f);
    unsigned short u = *(unsigned short*)&h;
    asm volatile("st.shared.b16 [%0], %1;" :: "r"(addr), "h"(u) : "memory");
}
__device__ __forceinline__ uint32_t packh2(float a, float b) {
    __half2 h = __float22half2_rn(make_float2(a, b));
    return *(uint32_t*)&h;
}
#define CP_ASYNC16(dst, src) \
    asm volatile("cp.async.cg.shared.global [%0], [%1], 16;" :: "r"(dst), "l"(src))
#define CP_COMMIT()  asm volatile("cp.async.commit_group;" ::: "memory")
#define CP_WAIT(n)   asm volatile("cp.async.wait_group %0;" :: "n"(n) : "memory")

__device__ __forceinline__ void mma_f16(float& c0, float& c1, float& c2, float& c3,
                                        uint32_t a0, uint32_t a1, uint32_t a2, uint32_t a3,
                                        uint32_t b0, uint32_t b1) {
    asm volatile("mma.sync.aligned.m16n8k16.row.col.f32.f16.f16.f32 "
        "{%0,%1,%2,%3}, {%4,%5,%6,%7}, {%8,%9}, {%0,%1,%2,%3};"
        : "+f"(c0), "+f"(c1), "+f"(c2), "+f"(c3)
        : "r"(a0), "r"(a1), "r"(a2), "r"(a3), "r"(b0), "r"(b1));
}

// ---------- prep ----------
__global__ void k_prep(const float* __restrict__ wqkv, const float* __restrict__ bqkv,
                       const float* __restrict__ wout,
                       const float* __restrict__ table, const int* __restrict__ rel,
                       const float* __restrict__ mask)
{
    const int idx = blockIdx.x * 256 + threadIdx.x;
    if (idx < 6 * 192 * 384) {
        const int grp = idx / (192 * 384);
        const int r   = idx - grp * (192 * 384);
        const int col = r / 384;
        const int k   = r - col * 384;
        const int e = col / 96, rr = col - e * 96, part = rr >> 5, d = rr & 31;
        const int h = grp * 2 + e;
        const float s = (part == 0) ? SCALE : 1.0f;
        g_wqkv_h[idx] = __float2half_rn(wqkv[(size_t)k * 1152 + part * 384 + h * 32 + d] * s);
    }
    if (idx < 384 * 384) {
        const int col = idx / 384, k = idx - col * 384;
        g_wout_h[idx] = __float2half_rn(wout[(size_t)k * 384 + col]);
    }
    if (idx < 1152) {
        const int grp = idx / 192, c = idx - grp * 192;
        const int e = c / 96, rr = c - e * 96, part = rr >> 5, d = rr & 31;
        const int h = grp * 2 + e;
        const float s = (part == 0) ? SCALE : 1.0f;
        g_bqkv_r[idx] = bqkv[part * 384 + h * 32 + d] * s;
    }
    if (idx < 64 * HH * LL * LL) {
        const int w  = idx / (HH * LL * LL);
        const int r2 = idx - w * (HH * LL * LL);
        const int h  = r2 / (LL * LL);
        const int ij = r2 - h * (LL * LL);
        g_bm[idx] = table[rel[ij] * HH + h] + mask[(size_t)w * (LL * LL) + ij];
    }
}

// ---------- fused ----------
extern __shared__ float smem[];

__global__ __launch_bounds__(NTHR, 1)
void k_fused(const float* __restrict__ x, const float* __restrict__ b_out,
             float* __restrict__ out)
{
    const int blk  = blockIdx.x;
    const int tid  = threadIdx.x;
    const int wid  = tid >> 5;
    const int lane = tid & 31;
    const int g    = lane >> 2;
    const int t    = lane & 3;
    const int wm   = wid >> 3;        // 0..1
    const int wn   = wid & 7;         // 0..7

    const uint32_t sb = smem_u32(smem);
    float* sa = smem + OFF_SA;

    const uint32_t xB   = sb + OFF_X * 4;
    const uint32_t ctxB = sb + OFF_CTX * 4;
    const uint32_t qhB  = sb + OFF_QH * 4;
    const uint32_t khB  = sb + OFF_KH * 4;
    const uint32_t vtB  = sb + OFF_VT * 4;
    const uint32_t alB  = sb + OFF_AL * 4;
    const uint32_t s1B  = sb + OFF_S1 * 4;
    const uint32_t s2B  = sb + OFF_S2 * 4;

    // ---- load x (fp32 -> fp16 A-layout) + zero vT (pads must stay 0) ----
    {
        const float* xg = x + (size_t)blk * (LL * EE);
        for (int u = tid; u < 49 * 48; u += NTHR) {
            const int row = u / 48, j = u - row * 48;
            const float4 v0 = *(const float4*)(xg + row * EE + j * 8);
            const float4 v1 = *(const float4*)(xg + row * EE + j * 8 + 4);
            const uint32_t p0 = packh2(v0.x, v0.y);
            const uint32_t p1 = packh2(v0.z, v0.w);
            const uint32_t p2 = packh2(v1.x, v1.y);
            const uint32_t p3 = packh2(v1.z, v1.w);
            asm volatile("st.shared.v4.b32 [%0], {%1,%2,%3,%4};" ::
                "r"(xB + (uint32_t)((row * 196 + j * 4) * 4)),
                "r"(p0), "r"(p1), "r"(p2), "r"(p3) : "memory");
        }
        for (int u = tid; u < 2304; u += NTHR)
            smem[OFF_VT + u] = 0.f;   // zero whole vT (j pads 49..63 stay 0)
    }
    // prefetch group 0 chunk 0: 192 cols x 96 halves (12 segs of 8)
    #pragma unroll
    for (int it = 0; it < 5; ++it) {
        const int u = tid + it * NTHR;
        if (u < 2304) {
            const int col = u / 12, seg = u - col * 12;
            CP_ASYNC16(s1B + (uint32_t)((col * 52 + seg * 4) * 4),
                       g_wqkv_h + col * 384 + seg * 8);
        }
    }
    CP_COMMIT();
    __syncthreads();

    // ================= 6 groups of 2 heads =================
    for (int grp = 0; grp < 6; ++grp) {
        const __half* Bsrc = g_wqkv_h + (size_t)grp * (192 * 384);
        const int h0 = grp * 2;

        float acc[2][3][4];
        #pragma unroll
        for (int a = 0; a < 2; ++a)
            #pragma unroll
            for (int b = 0; b < 3; ++b)
                #pragma unroll
                for (int q = 0; q < 4; ++q) acc[a][b][q] = 0.f;

        const int nb = wn * 24;

        // ---- QKV GEMM: 4 chunks of K=96 ----
        for (int c = 0; c < 4; ++c) {
            if (c < 3) {
                const __half* src = Bsrc + (c + 1) * 96;
                const uint32_t dstb = s1B + (uint32_t)(((c + 1) & 1) * S1_BUF * 4);
                #pragma unroll
                for (int it = 0; it < 5; ++it) {
                    const int u = tid + it * NTHR;
                    if (u < 2304) {
                        const int col = u / 12, seg = u - col * 12;
                        CP_ASYNC16(dstb + (uint32_t)((col * 52 + seg * 4) * 4),
                                   src + col * 384 + seg * 8);
                    }
                }
                CP_COMMIT();
                CP_WAIT(1);
            } else {
                CP_WAIT(0);
            }
            __syncthreads();

            const uint32_t sB = s1B + (uint32_t)((c & 1) * S1_BUF * 4);
            #pragma unroll
            for (int kt = 0; kt < 6; ++kt) {
                uint32_t af[2][4];
                const int kkb = c * 48 + kt * 8 + t;
                #pragma unroll
                for (int mt = 0; mt < 2; ++mt) {
                    const int r0 = min(wm * 32 + mt * 16 + g, 48);
                    const int r1 = min(wm * 32 + mt * 16 + g + 8, 48);
                    af[mt][0] = lds_u32(xB + (uint32_t)((r0 * 196 + kkb) * 4));
                    af[mt][1] = lds_u32(xB + (uint32_t)((r1 * 196 + kkb) * 4));
                    af[mt][2] = lds_u32(xB + (uint32_t)((r0 * 196 + kkb) * 4) + 16);
                    af[mt][3] = lds_u32(xB + (uint32_t)((r1 * 196 + kkb) * 4) + 16);
                }
                #pragma unroll
                for (int nt = 0; nt < 3; ++nt) {
                    const int col = nb + nt * 8 + g;
                    const uint32_t b0 = lds_u32(sB + (uint32_t)((col * 52 + kt * 8 + t) * 4));
                    const uint32_t b1 = lds_u32(sB + (uint32_t)((col * 52 + kt * 8 + t) * 4) + 16);
                    #pragma unroll
                    for (int mt = 0; mt < 2; ++mt)
                        mma_f16(acc[mt][nt][0], acc[mt][nt][1], acc[mt][nt][2], acc[mt][nt][3],
                                af[mt][0], af[mt][1], af[mt][2], af[mt][3], b0, b1);
                }
            }
            __syncthreads();
        }

        // prefetch NEXT group chunk 0 now (overlaps with attention below)
        if (grp < 5) {
            const __half* src = g_wqkv_h + (size_t)(grp + 1) * (192 * 384);
            #pragma unroll
            for (int it = 0; it < 5; ++it) {
                const int u = tid + it * NTHR;
                if (u < 2304) {
                    const int col = u / 12, seg = u - col * 12;
                    CP_ASYNC16(s1B + (uint32_t)((col * 52 + seg * 4) * 4),
                               src + col * 384 + seg * 8);
                }
            }
            CP_COMMIT();
        }

        // ---- epilogue: q,k (fp16 frag layouts) and vT ----
        #pragma unroll
        for (int mt = 0; mt < 2; ++mt) {
            const int r0 = wm * 32 + mt * 16 + g;
            const int r1 = r0 + 8;
            #pragma unroll
            for (int nt = 0; nt < 3; ++nt) {
                const int col0 = nb + nt * 8 + 2 * t;
                const float bb0 = g_bqkv_r[grp * 192 + col0];
                const float bb1 = g_bqkv_r[grp * 192 + col0 + 1];
                const int e = col0 / 96;
                const int rr = col0 - e * 96;
                const int part = rr >> 5;
                const int d = rr & 31;
                #pragma unroll
                for (int hv = 0; hv < 2; ++hv) {
                    const int r = hv ? r1 : r0;
                    if (r >= LL) continue;
                    const float v0 = acc[mt][nt][hv * 2 + 0] + bb0;
                    const float v1 = acc[mt][nt][hv * 2 + 1] + bb1;
                    if (part == 0) {
                        const uint32_t a0 = qhB + (uint32_t)(e * 3920 + r * 80 + d * 2);
                        sts_h(a0, v0); sts_h(a0 + 2, v1);
                    } else if (part == 1) {
                        const uint32_t a0 = khB + (uint32_t)(e * 4480 + r * 80 + d * 2);
                        sts_h(a0, v0); sts_h(a0 + 2, v1);
                    } else {
                        const uint32_t a0 = vtB + (uint32_t)(e * 4608 + d * 144 + r * 2);
                        sts_h(a0, v0); sts_h(a0 + 144, v1);   // (d+1) row
                    }
                }
            }
        }
        __syncthreads();

        // ---- scores via mma: warp = (e, tm, half) ----
        {
            const int e  = wid >> 3;
            const int tm = (wid >> 1) & 3;
            const int nt0 = (wid & 1) * 4;
            const int ntc = (wid & 1) ? 3 : 4;
            float sc[4][4];
            #pragma unroll
            for (int a = 0; a < 4; ++a)
                #pragma unroll
                for (int b = 0; b < 4; ++b) sc[a][b] = 0.f;
            const int r0 = min(tm * 16 + g, 48);
            const int r1 = min(tm * 16 + g + 8, 48);
            #pragma unroll
            for (int ks = 0; ks < 2; ++ks) {
                uint32_t a0 = lds_u32(qhB + (uint32_t)(e * 3920 + r0 * 80 + (ks * 8 + t) * 4));
                uint32_t a1 = lds_u32(qhB + (uint32_t)(e * 3920 + r1 * 80 + (ks * 8 + t) * 4));
                uint32_t a2 = lds_u32(qhB + (uint32_t)(e * 3920 + r0 * 80 + (ks * 8 + t) * 4) + 16);
                uint32_t a3 = lds_u32(qhB + (uint32_t)(e * 3920 + r1 * 80 + (ks * 8 + t) * 4) + 16);
                #pragma unroll
                for (int nt = 0; nt < 4; ++nt) {
                    if (nt >= ntc) break;
                    const int jr = (nt0 + nt) * 8 + g;
                    const uint32_t b0 = lds_u32(khB + (uint32_t)(e * 4480 + jr * 80 + (ks * 8 + t) * 4));
                    const uint32_t b1 = lds_u32(khB + (uint32_t)(e * 4480 + jr * 80 + (ks * 8 + t) * 4) + 16);
                    mma_f16(sc[nt][0], sc[nt][1], sc[nt][2], sc[nt][3], a0, a1, a2, a3, b0, b1);
                }
            }
            const float* bmb = g_bm + ((size_t)(blk & 63) * HH + (h0 + e)) * (LL * LL);
            float* sae = sa + e * 2548;
            const int i0 = tm * 16 + g;
            const int i1 = i0 + 8;
            #pragma unroll
            for (int nt = 0; nt < 4; ++nt) {
                if (nt >= ntc) break;
                const int j0 = (nt0 + nt) * 8 + 2 * t;
                if (j0 < LL) {
                    if (i0 < LL) sae[i0 * 52 + j0] = sc[nt][0] + bmb[i0 * LL + j0];
                    if (i1 < LL) sae[i1 * 52 + j0] = sc[nt][2] + bmb[i1 * LL + j0];
                }
                if (j0 + 1 < LL) {
                    if (i0 < LL) sae[i0 * 52 + j0 + 1] = sc[nt][1] + bmb[i0 * LL + j0 + 1];
                    if (i1 < LL) sae[i1 * 52 + j0 + 1] = sc[nt][3] + bmb[i1 * LL + j0 + 1];
                }
            }
        }
        __syncthreads();

        // ---- softmax (fp32) -> alpha (fp16, pads zeroed) ----
        for (int rr = wid; rr < 2 * LL; rr += 16) {
            const int e = rr / LL, i = rr - e * LL;
            float* row = sa + e * 2548 + i * 52;
            const float v0 = row[lane];
            const float v1 = (lane < 17) ? row[32 + lane] : -1e30f;
            float m = fmaxf(v0, v1);
            #pragma unroll
            for (int o = 16; o > 0; o >>= 1)
                m = fmaxf(m, __shfl_xor_sync(0xffffffffu, m, o));
            const float e0 = __expf(v0 - m);
            const float e1 = (lane < 17) ? __expf(v1 - m) : 0.f;
            float sm = e0 + e1;
            #pragma unroll
            for (int o = 16; o > 0; o >>= 1)
                sm += __shfl_xor_sync(0xffffffffu, sm, o);
            const float inv = 1.f / sm;
            const uint32_t ab = alB + (uint32_t)(e * 7056 + i * 144);
            sts_h(ab + lane * 2, e0 * inv);
            sts_h(ab + (32 + lane) * 2, (lane < 17) ? e1 * inv : 0.f);  // zeros j 49..63
        }
        __syncthreads();

        // ---- AV via mma: warp = (e, tm, tn-half) ----
        {
            const int e  = wid >> 3;
            const int tm = (wid >> 1) & 3;
            const int tnb = (wid & 1) * 2;
            float av[2][4];
            #pragma unroll
            for (int a = 0; a < 2; ++a)
                #pragma unroll
                for (int b = 0; b < 4; ++b) av[a][b] = 0.f;
            const int r0 = min(tm * 16 + g, 48);
            const int r1 = min(tm * 16 + g + 8, 48);
            #pragma unroll
            for (int ks = 0; ks < 4; ++ks) {
                uint32_t a0 = lds_u32(alB + (uint32_t)(e * 7056 + r0 * 144 + (ks * 8 + t) * 4));
                uint32_t a1 = lds_u32(alB + (uint32_t)(e * 7056 + r1 * 144 + (ks * 8 + t) * 4));
                uint32_t a2 = lds_u32(alB + (uint32_t)(e * 7056 + r0 * 144 + (ks * 8 + t) * 4) + 16);
                uint32_t a3 = lds_u32(alB + (uint32_t)(e * 7056 + r1 * 144 + (ks * 8 + t) * 4) + 16);
                #pragma unroll
                for (int nt = 0; nt < 2; ++nt) {
                    const int dr = (tnb + nt) * 8 + g;
                    const uint32_t b0 = lds_u32(vtB + (uint32_t)(e * 4608 + dr * 144 + (ks * 8 + t) * 4));
                    const uint32_t b1 = lds_u32(vtB + (uint32_t)(e * 4608 + dr * 144 + (ks * 8 + t) * 4) + 16);
                    mma_f16(av[nt][0], av[nt][1], av[nt][2], av[nt][3], a0, a1, a2, a3, b0, b1);
                }
            }
            const int i0 = tm * 16 + g;
            const int i1 = i0 + 8;
            #pragma unroll
            for (int nt = 0; nt < 2; ++nt) {
                const uint32_t cidx = (uint32_t)((h0 + e) * 16 + (tnb + nt) * 4 + t);
                if (i0 < LL)
                    asm volatile("st.shared.b32 [%0], %1;" ::
                        "r"(ctxB + (uint32_t)(i0 * 196 + cidx) * 4),
                        "r"(packh2(av[nt][0], av[nt][1])) : "memory");
                if (i1 < LL)
                    asm volatile("st.shared.b32 [%0], %1;" ::
                        "r"(ctxB + (uint32_t)(i1 * 196 + cidx) * 4),
                        "r"(packh2(av[nt][2], av[nt][3])) : "memory");
            }
        }
        __syncthreads();
    }

    // ================= out-proj: 49x384 @ 384x384, K-chunks of 64 =================
    {
        #pragma unroll
        for (int it = 0; it < 6; ++it) {
            const int u = tid + it * NTHR;
            const int col = u >> 3, seg = u & 7;
            CP_ASYNC16(s2B + (uint32_t)((col * 36 + seg * 4) * 4),
                       g_wout_h + col * 384 + seg * 8);
        }
        CP_COMMIT();

        float acc[2][6][4];
        #pragma unroll
        for (int a = 0; a < 2; ++a)
            #pragma unroll
            for (int b = 0; b < 6; ++b)
                #pragma unroll
                for (int q = 0; q < 4; ++q) acc[a][b][q] = 0.f;

        for (int c = 0; c < 6; ++c) {
            if (c < 5) {
                const __half* src = g_wout_h + (c + 1) * 64;
                const uint32_t dstb = s2B + (uint32_t)(((c + 1) & 1) * S2_BUF * 4);
                #pragma unroll
                for (int it = 0; it < 6; ++it) {
                    const int u = tid + it * NTHR;
                    const int col = u >> 3, seg = u & 7;
                    CP_ASYNC16(dstb + (uint32_t)((col * 36 + seg * 4) * 4),
                               src + col * 384 + seg * 8);
                }
                CP_COMMIT();
                CP_WAIT(1);
            } else {
                CP_WAIT(0);
            }
            __syncthreads();

            const uint32_t sB = s2B + (uint32_t)((c & 1) * S2_BUF * 4);
            #pragma unroll
            for (int kt = 0; kt < 4; ++kt) {
                uint32_t af[2][4];
                const int kkb = c * 32 + kt * 8 + t;
                #pragma unroll
                for (int mt = 0; mt < 2; ++mt) {
                    const int r0 = min(wm * 32 + mt * 16 + g, 48);
                    const int r1 = min(wm * 32 + mt * 16 + g + 8, 48);
                    af[mt][0] = lds_u32(ctxB + (uint32_t)((r0 * 196 + kkb) * 4));
                    af[mt][1] = lds_u32(ctxB + (uint32_t)((r1 * 196 + kkb) * 4));
                    af[mt][2] = lds_u32(ctxB + (uint32_t)((r0 * 196 + kkb) * 4) + 16);
                    af[mt][3] = lds_u32(ctxB + (uint32_t)((r1 * 196 + kkb) * 4) + 16);
                }
                #pragma unroll
                for (int nt = 0; nt < 6; ++nt) {
                    const int col = wn * 48 + nt * 8 + g;
                    const uint32_t b0 = lds_u32(sB + (uint32_t)((col * 36 + kt * 8 + t) * 4));
                    const uint32_t b1 = lds_u32(sB + (uint32_t)((col * 36 + kt * 8 + t) * 4) + 16);
                    #pragma unroll
                    for (int mt = 0; mt < 2; ++mt)
                        mma_f16(acc[mt][nt][0], acc[mt][nt][1], acc[mt][nt][2], acc[mt][nt][3],
                                af[mt][0], af[mt][1], af[mt][2], af[mt][3], b0, b1);
                }
            }
            __syncthreads();
        }

        float* outp = out + (size_t)blk * (LL * EE);
        #pragma unroll
        for (int mt = 0; mt < 2; ++mt) {
            const int r0 = wm * 32 + mt * 16 + g;
            const int r1 = r0 + 8;
            #pragma unroll
            for (int nt = 0; nt < 6; ++nt) {
                const int col = wn * 48 + nt * 8 + 2 * t;
                const float b0 = b_out[col], b1 = b_out[col + 1];
                if (r0 < LL) {
                    float2 o; o.x = acc[mt][nt][0] + b0; o.y = acc[mt][nt][1] + b1;
                    *(float2*)(outp + r0 * EE + col) = o;
                }
                if (r1 < LL) {
                    float2 o; o.x = acc[mt][nt][2] + b0; o.y = acc[mt][nt][3] + b1;
                    *(float2*)(outp + r1 * EE + col) = o;
                }
            }
        }
    }
}

// ---------- launch ----------
extern "C" void kernel_launch(void* const* d_in, const int* in_sizes, int n_in,
                              void* d_out, int out_size)
{
    const float* x    = (const float*)d_in[0];
    const float* mask = (const float*)d_in[1];
    const float* wqkv = (const float*)d_in[2];
    const float* bqkv = (const float*)d_in[3];
    const float* wout = (const float*)d_in[4];
    const float* bout = (const float*)d_in[5];
    const float* bt   = (const float*)d_in[6];
    const int*   rel  = (const int*)d_in[7];
    float* out = (float*)d_out;

    cudaFuncSetAttribute(k_fused, cudaFuncAttributeMaxDynamicSharedMemorySize, SMEM_B);

    k_prep<<<(64 * HH * LL * LL + 255) / 256, 256>>>(wqkv, bqkv, wout, bt, rel, mask);
    k_fused<<<4096, NTHR, SMEM_B>>>(x, bout, out);
}